// round 2
// baseline (speedup 1.0000x reference)
#include <cuda_runtime.h>
#include <math.h>

// Problem constants
#define NBATCH 8
#define CCH    256
#define TSEQ   1024
#define NHEAD  8
#define HDIM   32

// Scratch: K, Q, V in [N, H, T, D] layout; attn out in [N, T, C] layout.
__device__ float g_k[NBATCH * NHEAD * TSEQ * HDIM];
__device__ float g_q[NBATCH * NHEAD * TSEQ * HDIM];
__device__ float g_v[NBATCH * NHEAD * TSEQ * HDIM];
__device__ float g_attn[NBATCH * TSEQ * CCH];

// ---------------------------------------------------------------------------
// Kernel 1: KQV projection.
//   A[m, k] = seq[n, t, c=k] = image[n, k, t]   (m = n*1024 + t)
//   B = w_kqv [256, 768] row-major
//   out o in [0,768): which = o/256 (0=k,1=q,2=v), c = o%256, h = c/32, d = c%32
// Tiled SGEMM: BM=64, BN=64, BK=32, 256 threads, 4x4 register blocking.
// ---------------------------------------------------------------------------
__global__ __launch_bounds__(256) void kqv_gemm(const float* __restrict__ image,
                                                const float* __restrict__ w,
                                                const float* __restrict__ bias) {
    __shared__ float As[32][64];
    __shared__ float Bs[32][64];
    const int bm = blockIdx.y * 64;
    const int bn = blockIdx.x * 64;
    const int tid = threadIdx.x;
    const int tx = tid & 15;       // m direction (fast)
    const int ty = tid >> 4;       // o direction
    const int n  = bm >> 10;       // tile lies within one batch (64 | 1024)
    const int t0 = bm & 1023;

    float acc[4][4] = {};

    for (int k0 = 0; k0 < 256; k0 += 32) {
        #pragma unroll
        for (int l = 0; l < 8; l++) {
            int idx = l * 256 + tid;
            int kk = idx >> 6, mm = idx & 63;
            As[kk][mm] = image[n * 262144 + (k0 + kk) * 1024 + t0 + mm];
        }
        #pragma unroll
        for (int l = 0; l < 8; l++) {
            int idx = l * 256 + tid;
            int kk = idx >> 6, oo = idx & 63;
            Bs[kk][oo] = w[(k0 + kk) * 768 + bn + oo];
        }
        __syncthreads();
        #pragma unroll
        for (int kk = 0; kk < 32; kk++) {
            float ra[4], rb[4];
            #pragma unroll
            for (int i = 0; i < 4; i++) ra[i] = As[kk][tx + 16 * i];
            #pragma unroll
            for (int j = 0; j < 4; j++) rb[j] = Bs[kk][ty * 4 + j];
            #pragma unroll
            for (int i = 0; i < 4; i++)
                #pragma unroll
                for (int j = 0; j < 4; j++)
                    acc[i][j] += ra[i] * rb[j];
        }
        __syncthreads();
    }

    #pragma unroll
    for (int i = 0; i < 4; i++) {
        const int t = t0 + tx + 16 * i;
        #pragma unroll
        for (int j = 0; j < 4; j++) {
            const int o = bn + ty * 4 + j;
            float val = acc[i][j] + bias[o];
            const int which = o >> 8;
            const int c = o & 255;
            const int h = c >> 5;
            const int d = c & 31;
            float* dst = (which == 0) ? g_k : (which == 1) ? g_q : g_v;
            dst[((n * NHEAD + h) * TSEQ + t) * HDIM + d] = val;
        }
    }
}

// ---------------------------------------------------------------------------
// Kernel 2: causal flash attention. One thread = one query row.
// Block: 128 threads (query tile of 128). Grid: (8 q-tiles, 64 n*h).
// K/V tiles of 64 keys staged in shared; online softmax in registers.
// ---------------------------------------------------------------------------
__global__ __launch_bounds__(128) void attn_kernel() {
    const int qt = blockIdx.x;          // 0..7
    const int nh = blockIdx.y;          // 0..63  (n*8 + h)
    const int tid = threadIdx.x;
    const int tq = qt * 128 + tid;      // this thread's query row

    const float* Qb = g_q + (size_t)nh * TSEQ * HDIM;
    const float* Kb = g_k + (size_t)nh * TSEQ * HDIM;
    const float* Vb = g_v + (size_t)nh * TSEQ * HDIM;

    // Query row into registers (8 x float4 = 32 floats)
    float4 q4[8];
    const float4* qsrc = (const float4*)(Qb + (size_t)tq * HDIM);
    #pragma unroll
    for (int d4 = 0; d4 < 8; d4++) q4[d4] = qsrc[d4];

    float acc[32];
    #pragma unroll
    for (int d = 0; d < 32; d++) acc[d] = 0.0f;
    float mmax = -INFINITY;
    float lsum = 0.0f;

    __shared__ float4 Ks[64 * 8];   // 64 keys x 32 dims
    __shared__ float4 Vs[64 * 8];

    const float scale = 0.17677669529663687f;  // 1/sqrt(32)
    const int ntiles = qt * 2 + 2;             // key tiles needed (64-wide)

    for (int kt = 0; kt < ntiles; kt++) {
        __syncthreads();
        const float4* ksrc = (const float4*)(Kb + (size_t)kt * 64 * HDIM);
        const float4* vsrc = (const float4*)(Vb + (size_t)kt * 64 * HDIM);
        #pragma unroll
        for (int l = 0; l < 4; l++) {
            Ks[l * 128 + tid] = ksrc[l * 128 + tid];
            Vs[l * 128 + tid] = vsrc[l * 128 + tid];
        }
        __syncthreads();

        const int base = kt * 64;
        #pragma unroll 4
        for (int j = 0; j < 64; j++) {
            float s = 0.0f;
            #pragma unroll
            for (int d4 = 0; d4 < 8; d4++) {
                float4 k4 = Ks[j * 8 + d4];
                s += q4[d4].x * k4.x + q4[d4].y * k4.y
                   + q4[d4].z * k4.z + q4[d4].w * k4.w;
            }
            s *= scale;
            if (base + j <= tq) {
                if (s <= mmax) {
                    float p = __expf(s - mmax);
                    lsum += p;
                    #pragma unroll
                    for (int d4 = 0; d4 < 8; d4++) {
                        float4 v4 = Vs[j * 8 + d4];
                        acc[d4 * 4 + 0] += p * v4.x;
                        acc[d4 * 4 + 1] += p * v4.y;
                        acc[d4 * 4 + 2] += p * v4.z;
                        acc[d4 * 4 + 3] += p * v4.w;
                    }
                } else {
                    float r = __expf(mmax - s);   // expf(-inf)=0 on first key
                    mmax = s;
                    lsum = lsum * r + 1.0f;
                    #pragma unroll
                    for (int d4 = 0; d4 < 8; d4++) {
                        float4 v4 = Vs[j * 8 + d4];
                        acc[d4 * 4 + 0] = acc[d4 * 4 + 0] * r + v4.x;
                        acc[d4 * 4 + 1] = acc[d4 * 4 + 1] * r + v4.y;
                        acc[d4 * 4 + 2] = acc[d4 * 4 + 2] * r + v4.z;
                        acc[d4 * 4 + 3] = acc[d4 * 4 + 3] * r + v4.w;
                    }
                }
            }
        }
    }

    const float inv = 1.0f / lsum;
    const int n = nh >> 3;
    const int h = nh & 7;
    float4* dst = (float4*)(g_attn + ((size_t)(n * TSEQ + tq)) * CCH + h * HDIM);
    #pragma unroll
    for (int d4 = 0; d4 < 8; d4++) {
        dst[d4] = make_float4(acc[d4 * 4 + 0] * inv, acc[d4 * 4 + 1] * inv,
                              acc[d4 * 4 + 2] * inv, acc[d4 * 4 + 3] * inv);
    }
}

// ---------------------------------------------------------------------------
// Kernel 3: mix projection + bias + residual, stored to [N, C, H, W] output.
//   A[m, k] = g_attn[m*256 + k]  (contiguous rows)
//   B = w_mix [256, 256]
// ---------------------------------------------------------------------------
__global__ __launch_bounds__(256) void mix_gemm(const float* __restrict__ image,
                                                const float* __restrict__ w,
                                                const float* __restrict__ bias,
                                                float* __restrict__ out) {
    __shared__ float As[32][65];   // padded: written kk-major
    __shared__ float Bs[32][64];
    const int bm = blockIdx.y * 64;
    const int bn = blockIdx.x * 64;
    const int tid = threadIdx.x;
    const int tx = tid & 15;
    const int ty = tid >> 4;

    float acc[4][4] = {};

    for (int k0 = 0; k0 < 256; k0 += 32) {
        #pragma unroll
        for (int l = 0; l < 8; l++) {
            int idx = l * 256 + tid;
            int mm = idx >> 5, kk = idx & 31;   // contiguous k per row -> coalesced
            As[kk][mm] = g_attn[(size_t)(bm + mm) * 256 + k0 + kk];
        }
        #pragma unroll
        for (int l = 0; l < 8; l++) {
            int idx = l * 256 + tid;
            int kk = idx >> 6, oo = idx & 63;
            Bs[kk][oo] = w[(k0 + kk) * 256 + bn + oo];
        }
        __syncthreads();
        #pragma unroll
        for (int kk = 0; kk < 32; kk++) {
            float ra[4], rb[4];
            #pragma unroll
            for (int i = 0; i < 4; i++) ra[i] = As[kk][tx + 16 * i];
            #pragma unroll
            for (int j = 0; j < 4; j++) rb[j] = Bs[kk][ty * 4 + j];
            #pragma unroll
            for (int i = 0; i < 4; i++)
                #pragma unroll
                for (int j = 0; j < 4; j++)
                    acc[i][j] += ra[i] * rb[j];
        }
        __syncthreads();
    }

    #pragma unroll
    for (int j = 0; j < 4; j++) {
        const int o = bn + ty * 4 + j;
        const float bo = bias[o];
        #pragma unroll
        for (int i = 0; i < 4; i++) {
            const int m = bm + tx + 16 * i;
            const int n = m >> 10;
            const int t = m & 1023;
            const size_t gidx = (size_t)n * 262144 + (size_t)o * 1024 + t;
            out[gidx] = acc[i][j] + bo + image[gidx];
        }
    }
}

// ---------------------------------------------------------------------------
extern "C" void kernel_launch(void* const* d_in, const int* in_sizes, int n_in,
                              void* d_out, int out_size) {
    const float* image = (const float*)d_in[0];
    const float* w_kqv = (const float*)d_in[1];
    const float* b_kqv = (const float*)d_in[2];
    const float* w_mix = (const float*)d_in[3];
    const float* b_mix = (const float*)d_in[4];
    float* out = (float*)d_out;

    // KQV projection: M=8192, N=768
    dim3 gridA(768 / 64, 8192 / 64);
    kqv_gemm<<<gridA, 256>>>(image, w_kqv, b_kqv);

    // Attention: 8 query tiles x 64 (n,h) pairs
    dim3 gridB(8, 64);
    attn_kernel<<<gridB, 128>>>();

    // Mix + residual: M=8192, N=256
    dim3 gridC(256 / 64, 8192 / 64);
    mix_gemm<<<gridC, 256>>>(image, w_mix, b_mix, out);
}

// round 3
// speedup vs baseline: 1.0942x; 1.0942x over previous
#include <cuda_runtime.h>
#include <math.h>

// Problem constants
#define NBATCH 8
#define CCH    256
#define TSEQ   1024
#define NHEAD  8
#define HDIM   32

// Scratch. K/Q/V in [N, H, T, D]. g_attn TRANSPOSED: [C, N*T] (c-major rows).
__device__ float g_k[NBATCH * NHEAD * TSEQ * HDIM];
__device__ float g_q[NBATCH * NHEAD * TSEQ * HDIM];
__device__ float g_v[NBATCH * NHEAD * TSEQ * HDIM];
__device__ float g_attn[CCH * NBATCH * TSEQ];

// ---------------------------------------------------------------------------
// Kernel 1: KQV projection.  A[m,k] = image[n, k, t]  (m = n*1024 + t)
// B = w_kqv [256, 768].  64x64 tile, BK=32, 256 threads, 4x4 micro-tile,
// float4 shared reads (2 LDS.128 + 16 FFMA per kk).
// ---------------------------------------------------------------------------
__global__ __launch_bounds__(256) void kqv_gemm(const float* __restrict__ image,
                                                const float* __restrict__ w,
                                                const float* __restrict__ bias) {
    __shared__ float As[32][64];
    __shared__ float Bs[32][64];
    const int bm = blockIdx.y * 64;
    const int bn = blockIdx.x * 64;
    const int tid = threadIdx.x;
    const int tx = tid & 15;       // m direction: 4 consecutive rows
    const int ty = tid >> 4;       // o direction: 4 consecutive cols
    const int n  = bm >> 10;
    const int t0 = bm & 1023;

    float acc[4][4] = {};
    float4* As4 = (float4*)&As[0][0];
    float4* Bs4 = (float4*)&Bs[0][0];

    for (int k0 = 0; k0 < 256; k0 += 32) {
        #pragma unroll
        for (int l = 0; l < 2; l++) {
            int idx = l * 256 + tid;          // 512 float4 = 32 rows x 16
            int kk = idx >> 4, f4 = idx & 15;
            As4[idx] = *(const float4*)&image[n * 262144 + (k0 + kk) * 1024 + t0 + f4 * 4];
            Bs4[idx] = *(const float4*)&w[(k0 + kk) * 768 + bn + f4 * 4];
        }
        __syncthreads();
        #pragma unroll
        for (int kk = 0; kk < 32; kk++) {
            float4 a = *(const float4*)&As[kk][tx * 4];
            float4 b = *(const float4*)&Bs[kk][ty * 4];
            acc[0][0] += a.x * b.x; acc[0][1] += a.x * b.y; acc[0][2] += a.x * b.z; acc[0][3] += a.x * b.w;
            acc[1][0] += a.y * b.x; acc[1][1] += a.y * b.y; acc[1][2] += a.y * b.z; acc[1][3] += a.y * b.w;
            acc[2][0] += a.z * b.x; acc[2][1] += a.z * b.y; acc[2][2] += a.z * b.z; acc[2][3] += a.z * b.w;
            acc[3][0] += a.w * b.x; acc[3][1] += a.w * b.y; acc[3][2] += a.w * b.z; acc[3][3] += a.w * b.w;
        }
        __syncthreads();
    }

    // Store: thread owns 4 consecutive o (all within one head, one 'which').
    const int o0 = bn + ty * 4;
    const int which = o0 >> 8;
    const int c = o0 & 255;
    const int h = c >> 5;
    const int d0 = c & 31;
    float* dst = (which == 0) ? g_k : (which == 1) ? g_q : g_v;
    const float4 b4 = *(const float4*)&bias[o0];
    #pragma unroll
    for (int i = 0; i < 4; i++) {
        const int t = t0 + tx * 4 + i;
        float4 v = make_float4(acc[i][0] + b4.x, acc[i][1] + b4.y,
                               acc[i][2] + b4.z, acc[i][3] + b4.w);
        *(float4*)&dst[((size_t)(n * NHEAD + h) * TSEQ + t) * HDIM + d0] = v;
    }
}

// ---------------------------------------------------------------------------
// Kernel 2: causal flash attention. 1 thread = 1 query row, 128 q/block.
// Split dot accumulators (ILP), mask-free fast path for fully-visible tiles.
// ---------------------------------------------------------------------------
__global__ __launch_bounds__(128) void attn_kernel() {
    const int qt = (int)gridDim.x - 1 - (int)blockIdx.x;  // heavy tiles first
    const int nh = blockIdx.y;
    const int tid = threadIdx.x;
    const int tq = qt * 128 + tid;

    const float* Qb = g_q + (size_t)nh * TSEQ * HDIM;
    const float* Kb = g_k + (size_t)nh * TSEQ * HDIM;
    const float* Vb = g_v + (size_t)nh * TSEQ * HDIM;

    float4 q4[8];
    const float4* qsrc = (const float4*)(Qb + (size_t)tq * HDIM);
    #pragma unroll
    for (int d4 = 0; d4 < 8; d4++) q4[d4] = qsrc[d4];

    float acc[32];
    #pragma unroll
    for (int d = 0; d < 32; d++) acc[d] = 0.0f;
    float mmax = -INFINITY;
    float lsum = 0.0f;

    __shared__ float4 Ks[64 * 8];
    __shared__ float4 Vs[64 * 8];

    const float scale = 0.17677669529663687f;  // 1/sqrt(32)
    const int full_tiles = qt * 2;             // fully visible for every thread
    const int ntiles = full_tiles + 2;         // + 2 diagonal tiles

    for (int kt = 0; kt < ntiles; kt++) {
        __syncthreads();
        const float4* ksrc = (const float4*)(Kb + (size_t)kt * 64 * HDIM);
        const float4* vsrc = (const float4*)(Vb + (size_t)kt * 64 * HDIM);
        #pragma unroll
        for (int l = 0; l < 4; l++) {
            Ks[l * 128 + tid] = ksrc[l * 128 + tid];
            Vs[l * 128 + tid] = vsrc[l * 128 + tid];
        }
        __syncthreads();

        const bool full = (kt < full_tiles);
        const int base = kt * 64;

        if (full) {
            #pragma unroll 4
            for (int j = 0; j < 64; j++) {
                float s0 = 0.f, s1 = 0.f, s2 = 0.f, s3 = 0.f;
                #pragma unroll
                for (int d4 = 0; d4 < 8; d4 += 4) {
                    float4 k0 = Ks[j * 8 + d4 + 0], k1 = Ks[j * 8 + d4 + 1];
                    float4 k2 = Ks[j * 8 + d4 + 2], k3 = Ks[j * 8 + d4 + 3];
                    s0 += q4[d4 + 0].x * k0.x + q4[d4 + 0].y * k0.y + q4[d4 + 0].z * k0.z + q4[d4 + 0].w * k0.w;
                    s1 += q4[d4 + 1].x * k1.x + q4[d4 + 1].y * k1.y + q4[d4 + 1].z * k1.z + q4[d4 + 1].w * k1.w;
                    s2 += q4[d4 + 2].x * k2.x + q4[d4 + 2].y * k2.y + q4[d4 + 2].z * k2.z + q4[d4 + 2].w * k2.w;
                    s3 += q4[d4 + 3].x * k3.x + q4[d4 + 3].y * k3.y + q4[d4 + 3].z * k3.z + q4[d4 + 3].w * k3.w;
                }
                float s = ((s0 + s1) + (s2 + s3)) * scale;
                if (s <= mmax) {
                    float p = __expf(s - mmax);
                    lsum += p;
                    #pragma unroll
                    for (int d4 = 0; d4 < 8; d4++) {
                        float4 v4 = Vs[j * 8 + d4];
                        acc[d4 * 4 + 0] += p * v4.x; acc[d4 * 4 + 1] += p * v4.y;
                        acc[d4 * 4 + 2] += p * v4.z; acc[d4 * 4 + 3] += p * v4.w;
                    }
                } else {
                    float r = __expf(mmax - s);
                    mmax = s;
                    lsum = lsum * r + 1.0f;
                    #pragma unroll
                    for (int d4 = 0; d4 < 8; d4++) {
                        float4 v4 = Vs[j * 8 + d4];
                        acc[d4 * 4 + 0] = acc[d4 * 4 + 0] * r + v4.x;
                        acc[d4 * 4 + 1] = acc[d4 * 4 + 1] * r + v4.y;
                        acc[d4 * 4 + 2] = acc[d4 * 4 + 2] * r + v4.z;
                        acc[d4 * 4 + 3] = acc[d4 * 4 + 3] * r + v4.w;
                    }
                }
            }
        } else {
            #pragma unroll 2
            for (int j = 0; j < 64; j++) {
                float s0 = 0.f, s1 = 0.f, s2 = 0.f, s3 = 0.f;
                #pragma unroll
                for (int d4 = 0; d4 < 8; d4 += 4) {
                    float4 k0 = Ks[j * 8 + d4 + 0], k1 = Ks[j * 8 + d4 + 1];
                    float4 k2 = Ks[j * 8 + d4 + 2], k3 = Ks[j * 8 + d4 + 3];
                    s0 += q4[d4 + 0].x * k0.x + q4[d4 + 0].y * k0.y + q4[d4 + 0].z * k0.z + q4[d4 + 0].w * k0.w;
                    s1 += q4[d4 + 1].x * k1.x + q4[d4 + 1].y * k1.y + q4[d4 + 1].z * k1.z + q4[d4 + 1].w * k1.w;
                    s2 += q4[d4 + 2].x * k2.x + q4[d4 + 2].y * k2.y + q4[d4 + 2].z * k2.z + q4[d4 + 2].w * k2.w;
                    s3 += q4[d4 + 3].x * k3.x + q4[d4 + 3].y * k3.y + q4[d4 + 3].z * k3.z + q4[d4 + 3].w * k3.w;
                }
                float s = ((s0 + s1) + (s2 + s3)) * scale;
                if (base + j <= tq) {
                    if (s <= mmax) {
                        float p = __expf(s - mmax);
                        lsum += p;
                        #pragma unroll
                        for (int d4 = 0; d4 < 8; d4++) {
                            float4 v4 = Vs[j * 8 + d4];
                            acc[d4 * 4 + 0] += p * v4.x; acc[d4 * 4 + 1] += p * v4.y;
                            acc[d4 * 4 + 2] += p * v4.z; acc[d4 * 4 + 3] += p * v4.w;
                        }
                    } else {
                        float r = __expf(mmax - s);
                        mmax = s;
                        lsum = lsum * r + 1.0f;
                        #pragma unroll
                        for (int d4 = 0; d4 < 8; d4++) {
                            float4 v4 = Vs[j * 8 + d4];
                            acc[d4 * 4 + 0] = acc[d4 * 4 + 0] * r + v4.x;
                            acc[d4 * 4 + 1] = acc[d4 * 4 + 1] * r + v4.y;
                            acc[d4 * 4 + 2] = acc[d4 * 4 + 2] * r + v4.z;
                            acc[d4 * 4 + 3] = acc[d4 * 4 + 3] * r + v4.w;
                        }
                    }
                }
            }
        }
    }

    // Write to g_attn [C, N*T]: scalar stores, lane-contiguous (coalesced).
    const float inv = 1.0f / lsum;
    const int n = nh >> 3;
    const int h = nh & 7;
    const size_t mcol = (size_t)n * TSEQ + tq;
    #pragma unroll
    for (int d = 0; d < 32; d++) {
        g_attn[(size_t)(h * HDIM + d) * (NBATCH * TSEQ) + mcol] = acc[d] * inv;
    }
}

// ---------------------------------------------------------------------------
// Kernel 3: mix projection + bias + residual -> out [N, C, H*W].
//   A[m,k] = g_attn[k, m]  (k-major rows, m contiguous -- same shape as kqv A)
// ---------------------------------------------------------------------------
__global__ __launch_bounds__(256) void mix_gemm(const float* __restrict__ image,
                                                const float* __restrict__ w,
                                                const float* __restrict__ bias,
                                                float* __restrict__ out) {
    __shared__ float As[32][64];
    __shared__ float Bs[32][64];
    const int bm = blockIdx.y * 64;
    const int bn = blockIdx.x * 64;
    const int tid = threadIdx.x;
    const int tx = tid & 15;
    const int ty = tid >> 4;
    const int n  = bm >> 10;
    const int t0 = bm & 1023;

    float acc[4][4] = {};
    float4* As4 = (float4*)&As[0][0];
    float4* Bs4 = (float4*)&Bs[0][0];

    for (int k0 = 0; k0 < 256; k0 += 32) {
        #pragma unroll
        for (int l = 0; l < 2; l++) {
            int idx = l * 256 + tid;
            int kk = idx >> 4, f4 = idx & 15;
            As4[idx] = *(const float4*)&g_attn[(size_t)(k0 + kk) * 8192 + bm + f4 * 4];
            Bs4[idx] = *(const float4*)&w[(k0 + kk) * 256 + bn + f4 * 4];
        }
        __syncthreads();
        #pragma unroll
        for (int kk = 0; kk < 32; kk++) {
            float4 a = *(const float4*)&As[kk][tx * 4];
            float4 b = *(const float4*)&Bs[kk][ty * 4];
            acc[0][0] += a.x * b.x; acc[0][1] += a.x * b.y; acc[0][2] += a.x * b.z; acc[0][3] += a.x * b.w;
            acc[1][0] += a.y * b.x; acc[1][1] += a.y * b.y; acc[1][2] += a.y * b.z; acc[1][3] += a.y * b.w;
            acc[2][0] += a.z * b.x; acc[2][1] += a.z * b.y; acc[2][2] += a.z * b.z; acc[2][3] += a.z * b.w;
            acc[3][0] += a.w * b.x; acc[3][1] += a.w * b.y; acc[3][2] += a.w * b.z; acc[3][3] += a.w * b.w;
        }
        __syncthreads();
    }

    // Output: out[n, o, t] — t contiguous per thread? No: thread has 4 m (t)
    // per i and 4 o per j. Store float4 over the m direction per fixed o.
    #pragma unroll
    for (int j = 0; j < 4; j++) {
        const int o = bn + ty * 4 + j;
        const float bo = bias[o];
        const size_t gbase = (size_t)n * 262144 + (size_t)o * 1024 + t0 + tx * 4;
        float4 img = *(const float4*)&image[gbase];
        float4 v = make_float4(acc[0][j] + bo + img.x, acc[1][j] + bo + img.y,
                               acc[2][j] + bo + img.z, acc[3][j] + bo + img.w);
        *(float4*)&out[gbase] = v;
    }
}

// ---------------------------------------------------------------------------
extern "C" void kernel_launch(void* const* d_in, const int* in_sizes, int n_in,
                              void* d_out, int out_size) {
    const float* image = (const float*)d_in[0];
    const float* w_kqv = (const float*)d_in[1];
    const float* b_kqv = (const float*)d_in[2];
    const float* w_mix = (const float*)d_in[3];
    const float* b_mix = (const float*)d_in[4];
    float* out = (float*)d_out;

    dim3 gridA(768 / 64, 8192 / 64);
    kqv_gemm<<<gridA, 256>>>(image, w_kqv, b_kqv);

    dim3 gridB(8, 64);
    attn_kernel<<<gridB, 128>>>();

    dim3 gridC(256 / 64, 8192 / 64);
    mix_gemm<<<gridC, 256>>>(image, w_mix, b_mix, out);
}